// round 7
// baseline (speedup 1.0000x reference)
#include <cuda_runtime.h>

// HMM forward for CgpHmmCell (nCodons=2): 24 states, batch=2048, T=2000.
// One thread per sequence, 64 warps. Beta-rescaled states; emission values
// FOLDED into per-context transition coefficients (25-value table per ctx),
// cutting FMA-pipe ops from 37 to 31 per step. R5 loop shape (unroll 2,
// seq prefetch distance 2) retained.

#define T_LEN 2000
#define BATCH 2048

__device__ float g_coef[17];
__device__ float g_raw[6];
__device__ float g_pi[24];
__device__ float g_Btab[64 * 28];   // folded coef table [ctx][25 used, pad 28]

// ---------------------------------------------------------------------------
// Setup kernel: coefs (thread 0), then folded per-ctx table (all threads).
// ---------------------------------------------------------------------------
__global__ void setup_kernel(const float* __restrict__ w,
                             const float* __restrict__ ew,
                             const float* __restrict__ ik) {
    int tid = threadIdx.x;
    if (tid == 0) {
        float w12 = w[12];
        float d1 = 1.0f - w12 * w12;
        float d2 = 1.0f - w12 * w12 * w12;
        float a00, a01, a34, a314, a37, a310, a67, a617, a610,
              a920, a910, a164, a1614, a197, a1917, a2210, a2220;
        {
            float v0 = 1.0f - w[0], v1 = w[0];
            float m = fmaxf(v0, v1);
            float e0 = expf(v0 - m), e1 = expf(v1 - m);
            float s = e0 + e1;
            a00 = e0 / s; a01 = e1 / s;
        }
        {
            float v0 = w[1], v1 = w[3], v2 = d1, v3 = d2;
            float m = fmaxf(fmaxf(v0, v1), fmaxf(v2, v3));
            float e0 = expf(v0 - m), e1 = expf(v1 - m), e2 = expf(v2 - m), e3 = expf(v3 - m);
            float s = e0 + e1 + e2 + e3;
            a34 = e0 / s; a314 = e1 / s; a37 = e2 / s; a310 = e3 / s;
        }
        {
            float v0 = w[2], v1 = w[4], v2 = d1;
            float m = fmaxf(fmaxf(v0, v1), v2);
            float e0 = expf(v0 - m), e1 = expf(v1 - m), e2 = expf(v2 - m);
            float s = e0 + e1 + e2;
            a67 = e0 / s; a617 = e1 / s; a610 = e2 / s;
        }
        {
            float v0 = w[5], v1 = 1.0f - w[5];
            float m = fmaxf(v0, v1);
            float e0 = expf(v0 - m), e1 = expf(v1 - m);
            float s = e0 + e1;
            a920 = e0 / s; a910 = e1 / s;
        }
        {
            float v0 = w[6], v1 = 1.0f - w[9];
            float m = fmaxf(v0, v1);
            float e0 = expf(v0 - m), e1 = expf(v1 - m);
            float s = e0 + e1;
            a164 = e0 / s; a1614 = e1 / s;
        }
        {
            float v0 = w[7], v1 = 1.0f - w[10];
            float m = fmaxf(v0, v1);
            float e0 = expf(v0 - m), e1 = expf(v1 - m);
            float s = e0 + e1;
            a197 = e0 / s; a1917 = e1 / s;
        }
        {
            float v0 = w[8], v1 = 1.0f - w[11];
            float m = fmaxf(v0, v1);
            float e0 = expf(v0 - m), e1 = expf(v1 - m);
            float s = e0 + e1;
            a2210 = e0 / s; a2220 = e1 / s;
        }
        const float S6 = 1.0f / 6.0f, S36 = 1.0f / 36.0f, S216 = 1.0f / 216.0f;
        g_coef[0]  = a00;          g_coef[1]  = a01;
        g_coef[2]  = a34;          g_coef[3]  = a314;
        g_coef[4]  = a37;          g_coef[5]  = a310;
        g_coef[6]  = a67;          g_coef[7]  = a617 * S6;
        g_coef[8]  = a610;         g_coef[9]  = a920 * S6;
        g_coef[10] = a910;         g_coef[11] = a164;
        g_coef[12] = a1614;        g_coef[13] = a197 * S36;
        g_coef[14] = a1917 * S216; g_coef[15] = a2210 * S36;
        g_coef[16] = a2220 * S216;
        g_raw[0] = a617; g_raw[1] = a920; g_raw[2] = a197;
        g_raw[3] = a1917; g_raw[4] = a2210; g_raw[5] = a2220;
        {
            float m = -1e30f;
            for (int i = 0; i < 24; i++) m = fmaxf(m, ik[i]);
            float e[24]; float s = 0.0f;
            for (int i = 0; i < 24; i++) { e[i] = expf(ik[i] - m); s += e[i]; }
            for (int i = 0; i < 24; i++) g_pi[i] = e[i] / s;
        }
    }
    __syncthreads();

    // Folded table: for each ctx = pp*16 + p*4 + c, compute E_j(ctx) for
    // j=0..16 and write 25 products/values.
    for (int ctx = tid; ctx < 64; ctx += blockDim.x) {
        int pq = ctx >> 2;     // pp*4 + p
        int c  = ctx & 3;
        float E[17];
        for (int j = 0; j < 17; j++) {
            const float* p = ew + j * 64 + pq * 4;
            float v0 = p[0], v1 = p[1], v2 = p[2], v3 = p[3];
            float m = fmaxf(fmaxf(v0, v1), fmaxf(v2, v3));
            float e0 = expf(v0 - m), e1 = expf(v1 - m),
                  e2 = expf(v2 - m), e3 = expf(v3 - m);
            float ss = e0 + e1 + e2 + e3;
            float ec = (c == 0) ? e0 : (c == 1) ? e1 : (c == 2) ? e2 : e3;
            E[j] = ec / ss;
        }
        float* row = g_Btab + ctx * 28;
        row[0]  = g_coef[0]  * E[0];    // a00*E0
        row[1]  = g_coef[1]  * E[1];    // a01*E1
        row[2]  = E[2];
        row[3]  = E[3];
        row[4]  = g_coef[2]  * E[4];    // a34*E4
        row[5]  = g_coef[11] * E[4];    // a164*E4
        row[6]  = E[5];
        row[7]  = E[6];
        row[8]  = g_coef[4]  * E[7];    // a37*E7
        row[9]  = g_coef[6]  * E[7];    // a67*E7
        row[10] = g_coef[13] * E[7];    // a197s*E7
        row[11] = E[8];
        row[12] = E[9];
        row[13] = g_coef[5]  * E[10];   // a310*E10
        row[14] = g_coef[8]  * E[10];   // a610*E10
        row[15] = g_coef[10] * E[10];   // a910*E10
        row[16] = g_coef[15] * E[10];   // a2210s*E10
        row[17] = E[11];
        row[18] = E[12];
        row[19] = E[13];
        row[20] = 0.5f * E[13];
        row[21] = g_coef[3]  * E[14];   // a314*E14
        row[22] = g_coef[12] * E[14];   // a1614*E14
        row[23] = E[15];
        row[24] = E[16];
        row[25] = 0.0f; row[26] = 0.0f; row[27] = 0.0f;
    }
}

// ---------------------------------------------------------------------------
// Forward kernel
// ---------------------------------------------------------------------------
struct FRow { float4 r0, r1, r2, r3, r4, r5; float e16; };

__device__ __forceinline__ FRow loadF(const float* __restrict__ Tb, int ctx) {
    const float4* r = reinterpret_cast<const float4*>(Tb + ctx * 28);
    FRow f;
    f.r0 = r[0]; f.r1 = r[1]; f.r2 = r[2];
    f.r3 = r[3]; f.r4 = r[4]; f.r5 = r[5];
    f.e16 = Tb[ctx * 28 + 24];
    return f;
}

// One beta-rescaled step with fully folded coefficients (31 FMA-pipe ops).
__device__ __forceinline__ void stepF(const float (&s)[24], float (&d)[24],
                                      const FRow& f,
                                      float k617, float k1917,
                                      float k920, float k2220) {
    d[0]  = f.r0.x * s[0];
    d[1]  = f.r0.y * s[0];
    d[2]  = f.r0.z * s[1];
    d[3]  = f.r0.w * s[2];
    d[4]  = fmaf(f.r1.x, s[3], f.r1.y * s[16]);
    d[5]  = f.r1.z * s[4];
    d[6]  = f.r1.w * s[5];
    d[7]  = fmaf(f.r2.x, s[3], fmaf(f.r2.y, s[6], f.r2.z * s[19]));
    d[8]  = f.r2.w * s[7];
    d[9]  = f.r3.x * s[8];
    d[10] = fmaf(f.r3.y, s[3], fmaf(f.r3.z, s[6], fmaf(f.r3.w, s[9], f.r4.x * s[22])));
    d[11] = f.r4.y * s[10];
    d[12] = f.r4.z * s[11];
    d[13] = fmaf(f.r4.w, s[12], f.r5.x * s[13]);
    d[14] = fmaf(f.r5.y, s[3], f.r5.z * s[16]);
    d[15] = f.r5.w * s[14];
    d[16] = f.e16  * s[15];
    d[17] = fmaf(k617, s[6], k1917 * s[19]);
    d[18] = s[17]; d[19] = s[18];
    d[20] = fmaf(k920, s[9], k2220 * s[22]);
    d[21] = s[20]; d[22] = s[21];
    d[23] = fmaf(0.0833333333333333f, s[13], 0.166666666666667f * s[23]);
}

__device__ __forceinline__ float sum24(const float (&a)[24]) {
    float s01 = (a[0] + a[1])   + (a[2] + a[3]);
    float s23 = (a[4] + a[5])   + (a[6] + a[7]);
    float s45 = (a[8] + a[9])   + (a[10] + a[11]);
    float s67 = (a[12] + a[13]) + (a[14] + a[15]);
    float s89 = (a[16] + a[17]) + (a[18] + a[19]);
    float sab = (a[20] + a[21]) + (a[22] + a[23]);
    return ((s01 + s23) + (s45 + s67)) + (s89 + sab);
}

__global__ __launch_bounds__(32, 1)
void forward_kernel(const int* __restrict__ seq, float* __restrict__ out) {
    __shared__ __align__(16) float Tb[64 * 28];
    {
        const float4* src = reinterpret_cast<const float4*>(g_Btab);
        float4* dst = reinterpret_cast<float4*>(Tb);
        for (int i = threadIdx.x; i < 64 * 28 / 4; i += 32) dst[i] = src[i];
    }
    __syncthreads();

    float k617  = g_coef[7],  k1917 = g_coef[14];
    float k920  = g_coef[9],  k2220 = g_coef[16];
    float a00   = g_coef[0],  a01   = g_coef[1];
    float a34   = g_coef[2],  a314  = g_coef[3];
    float a37   = g_coef[4],  a310  = g_coef[5];
    float a67   = g_coef[6],  a610  = g_coef[8];
    float a910  = g_coef[10], a164  = g_coef[11];
    float a1614 = g_coef[12];
    float r617 = g_raw[0], r920 = g_raw[1], r197 = g_raw[2],
          r1917 = g_raw[3], r2210 = g_raw[4], r2220 = g_raw[5];

    int b = blockIdx.x * 32 + threadIdx.x;
    const int4* q4 = reinterpret_cast<const int4*>(seq + b * T_LEN);

    float A[24], B[24];
    float P[24];
    #pragma unroll
    for (int i = 0; i < 24; i++) P[i] = g_pi[i];

    // t=1: pure transition step (raw coefs), then convert to beta scale.
    {
        float t0  = a00 * P[0];
        float t1  = a01 * P[0];
        float t4  = fmaf(a34,  P[3], a164 * P[16]);
        float t7  = fmaf(a37,  P[3], fmaf(a67,  P[6], r197 * P[19]));
        float t10 = fmaf(a310, P[3], fmaf(a610, P[6], fmaf(a910, P[9], r2210 * P[22])));
        float t13 = fmaf(0.5f, P[13], P[12]);
        float t14 = fmaf(a314, P[3], a1614 * P[16]);
        float t17 = fmaf(r617, P[6], r1917 * P[19]);
        float t20 = fmaf(r920, P[9], r2220 * P[22]);
        float t23 = fmaf(0.5f, P[13], P[23]);
        B[0] = t0;    B[1] = t1;    B[2] = P[1];  B[3] = P[2];
        B[4] = t4;    B[5] = P[4];  B[6] = P[5];  B[7] = t7;
        B[8] = P[7];  B[9] = P[8];  B[10] = t10;  B[11] = P[10];
        B[12] = P[11]; B[13] = t13; B[14] = t14;  B[15] = P[14];
        B[16] = P[15];
        B[17] = t17;
        B[18] = 6.0f  * P[17];
        B[19] = 36.0f * P[18];
        B[20] = t20;
        B[21] = 6.0f  * P[20];
        B[22] = 36.0f * P[21];
        B[23] = t23;
    }

    int4 v = q4[0];
    {
        int c2 = ((((v.x << 2) | v.y) << 2) | v.z) & 63;
        int c3 = ((c2 << 2) | v.w) & 63;
        FRow f2 = loadF(Tb, c2), f3 = loadF(Tb, c3);
        stepF(B, A, f2, k617, k1917, k920, k2220);   // t=2
        stepF(A, B, f3, k617, k1917, k920, k2220);   // t=3
    }
    int ctx = ((((v.y << 2) | v.z) << 2) | v.w) & 63;

    float loglik = -3.58351893845611f;   // 2*ln(1/6)

    // Main loop: seq int4 prefetch distance 2, compiler-unrolled by 2.
    int4 u0 = q4[1];
    int4 u1 = q4[2];
    #pragma unroll 2
    for (int j = 1; j < 500; ++j) {
        int jn = (j < 498) ? j + 2 : 499;
        int4 up = q4[jn];
        int c0 = ((ctx << 2) | u0.x) & 63;
        int c1 = ((c0  << 2) | u0.y) & 63;
        int c2 = ((c1  << 2) | u0.z) & 63;
        int c3 = ((c2  << 2) | u0.w) & 63;
        ctx = c3;
        FRow f0 = loadF(Tb, c0);
        FRow f1 = loadF(Tb, c1);
        FRow f2 = loadF(Tb, c2);
        FRow f3 = loadF(Tb, c3);
        stepF(B, A, f0, k617, k1917, k920, k2220);
        stepF(A, B, f1, k617, k1917, k920, k2220);
        stepF(B, A, f2, k617, k1917, k920, k2220);
        stepF(A, B, f3, k617, k1917, k920, k2220);
        if ((j & 3) == 3) {
            float S = sum24(B);
            loglik += __logf(S);
            float inv = __fdividef(1.0f, S);
            #pragma unroll
            for (int i = 0; i < 24; i++) B[i] *= inv;
        }
        u0 = u1; u1 = up;
    }

    // Final beta -> alpha mass correction: sum(beta_j / d_j).
    const float S6 = 1.0f / 6.0f, S36 = 1.0f / 36.0f;
    float Sf = (B[0] + B[1]) + (B[2] + B[3]) + (B[4] + B[5]) + (B[6] + B[7])
             + (B[8] + B[9]) + (B[10] + B[11]) + (B[12] + B[13]) + (B[14] + B[15])
             + (B[16] + B[17]) + (B[20] + B[23])
             + S6 * (B[18] + B[21]) + S36 * (B[19] + B[22]);
    loglik += __logf(Sf);

    out[b] = loglik;
}

// ---------------------------------------------------------------------------
// Launch
// ---------------------------------------------------------------------------
extern "C" void kernel_launch(void* const* d_in, const int* in_sizes, int n_in,
                              void* d_out, int out_size) {
    const float* transition_kernel = (const float*)d_in[0];
    const float* emission_kernel   = (const float*)d_in[1];
    const float* init_kernel       = (const float*)d_in[2];
    const int*   seq               = (const int*)d_in[3];
    float* out = (float*)d_out;

    setup_kernel<<<1, 256>>>(transition_kernel, emission_kernel, init_kernel);
    forward_kernel<<<BATCH / 32, 32>>>(seq, out);
}

// round 8
// speedup vs baseline: 1.5994x; 1.5994x over previous
#include <cuda_runtime.h>

// HMM forward for CgpHmmCell (nCodons=2): 24 states, batch=2048, T=2000.
// Lane-parallel: one WARP per sequence, one LANE per state (24 active).
// Uniform 4-source FMA pattern per lane; cross-state gather via shfl.
// 2048 warps -> 4 warps/SMSP on 128 SMs. Beta-rescaled states.

#define T_LEN 2000
#define BATCH 2048
#define WPB   16          // warps per block
#define BLOCK (WPB * 32)  // 512 threads

__device__ int4   g_srcs[32];     // per-lane source lanes
__device__ float4 g_cpre[32];     // per-lane prescaled (beta) coefficients
__device__ float4 g_craw[32];     // per-lane raw coefficients (t=1 step)
__device__ float  g_dscale[32];   // beta scale per lane
__device__ float  g_invd[32];     // 1/dscale
__device__ float  g_pi[24];
__device__ float  g_Etab[64 * 32]; // [ctx][lane]: E for lanes 0..16, 1.0 for 17..23, 0 for 24..31

// ---------------------------------------------------------------------------
// Setup
// ---------------------------------------------------------------------------
__global__ void setup_kernel(const float* __restrict__ w,
                             const float* __restrict__ ew,
                             const float* __restrict__ ik) {
    int tid = threadIdx.x;
    if (tid == 0) {
        float w12 = w[12];
        float d1 = 1.0f - w12 * w12;
        float d2 = 1.0f - w12 * w12 * w12;
        float a00, a01, a34, a314, a37, a310, a67, a617, a610,
              a920, a910, a164, a1614, a197, a1917, a2210, a2220;
        {
            float v0 = 1.0f - w[0], v1 = w[0];
            float m = fmaxf(v0, v1);
            float e0 = expf(v0 - m), e1 = expf(v1 - m);
            float s = e0 + e1;
            a00 = e0 / s; a01 = e1 / s;
        }
        {
            float v0 = w[1], v1 = w[3], v2 = d1, v3 = d2;
            float m = fmaxf(fmaxf(v0, v1), fmaxf(v2, v3));
            float e0 = expf(v0 - m), e1 = expf(v1 - m), e2 = expf(v2 - m), e3 = expf(v3 - m);
            float s = e0 + e1 + e2 + e3;
            a34 = e0 / s; a314 = e1 / s; a37 = e2 / s; a310 = e3 / s;
        }
        {
            float v0 = w[2], v1 = w[4], v2 = d1;
            float m = fmaxf(fmaxf(v0, v1), v2);
            float e0 = expf(v0 - m), e1 = expf(v1 - m), e2 = expf(v2 - m);
            float s = e0 + e1 + e2;
            a67 = e0 / s; a617 = e1 / s; a610 = e2 / s;
        }
        {
            float v0 = w[5], v1 = 1.0f - w[5];
            float m = fmaxf(v0, v1);
            float e0 = expf(v0 - m), e1 = expf(v1 - m);
            float s = e0 + e1;
            a920 = e0 / s; a910 = e1 / s;
        }
        {
            float v0 = w[6], v1 = 1.0f - w[9];
            float m = fmaxf(v0, v1);
            float e0 = expf(v0 - m), e1 = expf(v1 - m);
            float s = e0 + e1;
            a164 = e0 / s; a1614 = e1 / s;
        }
        {
            float v0 = w[7], v1 = 1.0f - w[10];
            float m = fmaxf(v0, v1);
            float e0 = expf(v0 - m), e1 = expf(v1 - m);
            float s = e0 + e1;
            a197 = e0 / s; a1917 = e1 / s;
        }
        {
            float v0 = w[8], v1 = 1.0f - w[11];
            float m = fmaxf(v0, v1);
            float e0 = expf(v0 - m), e1 = expf(v1 - m);
            float s = e0 + e1;
            a2210 = e0 / s; a2220 = e1 / s;
        }
        const float S6 = 1.0f / 6.0f, S36 = 1.0f / 36.0f, S216 = 1.0f / 216.0f;

        // defaults: self-source, zero coef, unit scale
        for (int l = 0; l < 32; l++) {
            g_srcs[l]   = make_int4(l, l, l, l);
            g_cpre[l]   = make_float4(0.f, 0.f, 0.f, 0.f);
            g_craw[l]   = make_float4(0.f, 0.f, 0.f, 0.f);
            g_dscale[l] = 1.0f;
            g_invd[l]   = 1.0f;
        }
        // lane tables: sources + coefs (pre = beta-rescaled, raw = t=1 step)
        g_srcs[0]  = make_int4(0, 0, 0, 0);
        g_cpre[0]  = make_float4(a00, 0, 0, 0);           g_craw[0]  = g_cpre[0];
        g_srcs[1]  = make_int4(0, 1, 1, 1);
        g_cpre[1]  = make_float4(a01, 0, 0, 0);           g_craw[1]  = g_cpre[1];
        g_srcs[2]  = make_int4(1, 2, 2, 2);
        g_cpre[2]  = make_float4(1, 0, 0, 0);             g_craw[2]  = g_cpre[2];
        g_srcs[3]  = make_int4(2, 3, 3, 3);
        g_cpre[3]  = make_float4(1, 0, 0, 0);             g_craw[3]  = g_cpre[3];
        g_srcs[4]  = make_int4(3, 16, 4, 4);
        g_cpre[4]  = make_float4(a34, a164, 0, 0);        g_craw[4]  = g_cpre[4];
        g_srcs[5]  = make_int4(4, 5, 5, 5);
        g_cpre[5]  = make_float4(1, 0, 0, 0);             g_craw[5]  = g_cpre[5];
        g_srcs[6]  = make_int4(5, 6, 6, 6);
        g_cpre[6]  = make_float4(1, 0, 0, 0);             g_craw[6]  = g_cpre[6];
        g_srcs[7]  = make_int4(3, 6, 19, 7);
        g_cpre[7]  = make_float4(a37, a67, a197 * S36, 0);
        g_craw[7]  = make_float4(a37, a67, a197, 0);
        g_srcs[8]  = make_int4(7, 8, 8, 8);
        g_cpre[8]  = make_float4(1, 0, 0, 0);             g_craw[8]  = g_cpre[8];
        g_srcs[9]  = make_int4(8, 9, 9, 9);
        g_cpre[9]  = make_float4(1, 0, 0, 0);             g_craw[9]  = g_cpre[9];
        g_srcs[10] = make_int4(3, 6, 9, 22);
        g_cpre[10] = make_float4(a310, a610, a910, a2210 * S36);
        g_craw[10] = make_float4(a310, a610, a910, a2210);
        g_srcs[11] = make_int4(10, 11, 11, 11);
        g_cpre[11] = make_float4(1, 0, 0, 0);             g_craw[11] = g_cpre[11];
        g_srcs[12] = make_int4(11, 12, 12, 12);
        g_cpre[12] = make_float4(1, 0, 0, 0);             g_craw[12] = g_cpre[12];
        g_srcs[13] = make_int4(12, 13, 13, 13);
        g_cpre[13] = make_float4(1, 0.5f, 0, 0);          g_craw[13] = g_cpre[13];
        g_srcs[14] = make_int4(3, 16, 14, 14);
        g_cpre[14] = make_float4(a314, a1614, 0, 0);      g_craw[14] = g_cpre[14];
        g_srcs[15] = make_int4(14, 15, 15, 15);
        g_cpre[15] = make_float4(1, 0, 0, 0);             g_craw[15] = g_cpre[15];
        g_srcs[16] = make_int4(15, 16, 16, 16);
        g_cpre[16] = make_float4(1, 0, 0, 0);             g_craw[16] = g_cpre[16];
        g_srcs[17] = make_int4(6, 19, 17, 17);
        g_cpre[17] = make_float4(a617 * S6, a1917 * S216, 0, 0);
        g_craw[17] = make_float4(a617, a1917, 0, 0);
        g_srcs[18] = make_int4(17, 18, 18, 18);
        g_cpre[18] = make_float4(1, 0, 0, 0);             g_craw[18] = g_cpre[18];
        g_srcs[19] = make_int4(18, 19, 19, 19);
        g_cpre[19] = make_float4(1, 0, 0, 0);             g_craw[19] = g_cpre[19];
        g_srcs[20] = make_int4(9, 22, 20, 20);
        g_cpre[20] = make_float4(a920 * S6, a2220 * S216, 0, 0);
        g_craw[20] = make_float4(a920, a2220, 0, 0);
        g_srcs[21] = make_int4(20, 21, 21, 21);
        g_cpre[21] = make_float4(1, 0, 0, 0);             g_craw[21] = g_cpre[21];
        g_srcs[22] = make_int4(21, 22, 22, 22);
        g_cpre[22] = make_float4(1, 0, 0, 0);             g_craw[22] = g_cpre[22];
        g_srcs[23] = make_int4(13, 23, 23, 23);
        g_cpre[23] = make_float4(S6 * 0.5f, S6, 0, 0);
        g_craw[23] = make_float4(0.5f, 1.0f, 0, 0);
        // beta scales
        g_dscale[18] = 6.0f;  g_invd[18] = S6;
        g_dscale[19] = 36.0f; g_invd[19] = S36;
        g_dscale[21] = 6.0f;  g_invd[21] = S6;
        g_dscale[22] = 36.0f; g_invd[22] = S36;
        // pi
        {
            float m = -1e30f;
            for (int i = 0; i < 24; i++) m = fmaxf(m, ik[i]);
            float e[24]; float s = 0.0f;
            for (int i = 0; i < 24; i++) { e[i] = expf(ik[i] - m); s += e[i]; }
            for (int i = 0; i < 24; i++) g_pi[i] = e[i] / s;
        }
    }
    __syncthreads();

    // E table: [ctx][lane], stride 32 (bank = lane, conflict-free).
    for (int idx = tid; idx < 64 * 32; idx += blockDim.x) {
        int ctx = idx >> 5;
        int l   = idx & 31;
        float val;
        if (l < 17) {
            int pq = ctx >> 2;
            int c  = ctx & 3;
            const float* p = ew + l * 64 + pq * 4;
            float v0 = p[0], v1 = p[1], v2 = p[2], v3 = p[3];
            float m = fmaxf(fmaxf(v0, v1), fmaxf(v2, v3));
            float e0 = expf(v0 - m), e1 = expf(v1 - m),
                  e2 = expf(v2 - m), e3 = expf(v3 - m);
            float ss = e0 + e1 + e2 + e3;
            float ec = (c == 0) ? e0 : (c == 1) ? e1 : (c == 2) ? e2 : e3;
            val = ec / ss;
        } else if (l < 24) {
            val = 1.0f;     // E folded into beta coefs for lanes 17..23
        } else {
            val = 0.0f;     // idle lanes
        }
        g_Etab[idx] = val;
    }
}

// ---------------------------------------------------------------------------
// Forward kernel: one warp per sequence, one lane per state.
// ---------------------------------------------------------------------------
__global__ __launch_bounds__(BLOCK)
void forward_kernel(const int* __restrict__ seq, float* __restrict__ out) {
    __shared__ __align__(16) float Tb[64 * 32];
    {
        const float4* src = reinterpret_cast<const float4*>(g_Etab);
        float4* dst = reinterpret_cast<float4*>(Tb);
        // 2048 floats = 512 float4 = exactly 1 per thread
        dst[threadIdx.x] = src[threadIdx.x];
    }
    __syncthreads();

    const int lane = threadIdx.x & 31;
    const int wid  = blockIdx.x * WPB + (threadIdx.x >> 5);   // sequence id

    const int4   si = g_srcs[lane];
    const float4 cp = g_cpre[lane];
    const float  dsc = g_dscale[lane];
    const float  invd = g_invd[lane];

    const int4* q4 = reinterpret_cast<const int4*>(seq + wid * T_LEN);

    float beta = (lane < 24) ? g_pi[lane] : 0.0f;

    // ---- t=1: raw-coef transition step (uniform E absorbed), then beta scale
    {
        const float4 cr = g_craw[lane];
        float v0 = beta;
        float s0 = __shfl_sync(0xffffffffu, v0, si.x);
        float s1 = __shfl_sync(0xffffffffu, v0, si.y);
        float s2 = __shfl_sync(0xffffffffu, v0, si.z);
        float s3 = __shfl_sync(0xffffffffu, v0, si.w);
        float acc = fmaf(cr.y, s1, cr.x * s0);
        acc = fmaf(cr.z, s2, acc);
        acc = fmaf(cr.w, s3, acc);
        beta = dsc * acc;
    }

    float ll = -3.58351893845611f;   // 2 * ln(1/6)

    // step macro-equivalent lambda
    auto step = [&](int c) {
        float v0 = beta;
        float s0 = __shfl_sync(0xffffffffu, v0, si.x);
        float s1 = __shfl_sync(0xffffffffu, v0, si.y);
        float s2 = __shfl_sync(0xffffffffu, v0, si.z);
        float s3 = __shfl_sync(0xffffffffu, v0, si.w);
        float acc = fmaf(cp.y, s1, cp.x * s0);
        acc = fmaf(cp.z, s2, acc);
        acc = fmaf(cp.w, s3, acc);
        beta = Tb[(c << 5) + lane] * acc;
    };

    // ---- t=2, t=3
    int4 v = q4[0];
    int ctx;
    {
        int c2 = ((v.x << 4) | (v.y << 2) | v.z) & 63;
        step(c2);
        int c3 = ((c2 << 2) | v.w) & 63;
        step(c3);
        ctx = c3;
    }

    // ---- main loop: blocks of 4 steps, seq prefetch distance 2
    int4 u0 = q4[1];
    int4 u1 = q4[2];
    for (int j = 1; j < 500; ++j) {
        int jn = (j < 498) ? j + 2 : 499;
        int4 up = q4[jn];
        int c0 = ((ctx << 2) | u0.x) & 63;
        step(c0);
        int c1 = ((c0 << 2) | u0.y) & 63;
        step(c1);
        int c2 = ((c1 << 2) | u0.z) & 63;
        step(c2);
        int c3 = ((c2 << 2) | u0.w) & 63;
        step(c3);
        ctx = c3;
        if ((j & 3) == 3) {
            float t = beta;
            t += __shfl_xor_sync(0xffffffffu, t, 16);
            t += __shfl_xor_sync(0xffffffffu, t, 8);
            t += __shfl_xor_sync(0xffffffffu, t, 4);
            t += __shfl_xor_sync(0xffffffffu, t, 2);
            t += __shfl_xor_sync(0xffffffffu, t, 1);
            ll += __logf(t);
            beta *= __fdividef(1.0f, t);
        }
        u0 = u1; u1 = up;
    }

    // ---- final beta -> alpha mass correction
    {
        float t = beta * invd;
        t += __shfl_xor_sync(0xffffffffu, t, 16);
        t += __shfl_xor_sync(0xffffffffu, t, 8);
        t += __shfl_xor_sync(0xffffffffu, t, 4);
        t += __shfl_xor_sync(0xffffffffu, t, 2);
        t += __shfl_xor_sync(0xffffffffu, t, 1);
        ll += __logf(t);
    }

    if (lane == 0) out[wid] = ll;
}

// ---------------------------------------------------------------------------
// Launch
// ---------------------------------------------------------------------------
extern "C" void kernel_launch(void* const* d_in, const int* in_sizes, int n_in,
                              void* d_out, int out_size) {
    const float* transition_kernel = (const float*)d_in[0];
    const float* emission_kernel   = (const float*)d_in[1];
    const float* init_kernel       = (const float*)d_in[2];
    const int*   seq               = (const int*)d_in[3];
    float* out = (float*)d_out;

    setup_kernel<<<1, 256>>>(transition_kernel, emission_kernel, init_kernel);
    forward_kernel<<<BATCH / WPB, BLOCK>>>(seq, out);
}

// round 9
// speedup vs baseline: 2.5546x; 1.5972x over previous
#include <cuda_runtime.h>

// HMM forward CgpHmmCell (nCodons=2): 24 states + 2 helper lanes, batch=2048, T=2000.
// One warp per sequence, one lane per state. High-fan-in states 7/10 split onto
// helper lanes 25/24 so every lane has <=2 sources: 2 shuffles + 1 LDS per step.

#define T_LEN 2000
#define BATCH 2048
#define WPB   4
#define BLOCK (WPB * 32)

__device__ int2   g_src[32];      // per-lane source lanes (s0, s1)
__device__ float2 g_cp[32];       // per-lane beta-rescaled coefficients
__device__ float2 g_cr[32];       // per-lane raw coefficients (t=1 step)
__device__ float  g_dsc[32];      // beta scale applied after t=1
__device__ float  g_invd[32];     // 1/dsc for final correction
__device__ float  g_pi[24];
__device__ float  g_Etab[64 * 32]; // [ctx][lane] destination-state emission factor

// ---------------------------------------------------------------------------
// Setup
// ---------------------------------------------------------------------------
__global__ void setup_kernel(const float* __restrict__ w,
                             const float* __restrict__ ew,
                             const float* __restrict__ ik) {
    int tid = threadIdx.x;
    if (tid == 0) {
        float w12 = w[12];
        float d1 = 1.0f - w12 * w12;
        float d2 = 1.0f - w12 * w12 * w12;
        float a00, a01, a34, a314, a37, a310, a67, a617, a610,
              a920, a910, a164, a1614, a197, a1917, a2210, a2220;
        {
            float v0 = 1.0f - w[0], v1 = w[0];
            float m = fmaxf(v0, v1);
            float e0 = expf(v0 - m), e1 = expf(v1 - m);
            float s = e0 + e1;
            a00 = e0 / s; a01 = e1 / s;
        }
        {
            float v0 = w[1], v1 = w[3], v2 = d1, v3 = d2;
            float m = fmaxf(fmaxf(v0, v1), fmaxf(v2, v3));
            float e0 = expf(v0 - m), e1 = expf(v1 - m), e2 = expf(v2 - m), e3 = expf(v3 - m);
            float s = e0 + e1 + e2 + e3;
            a34 = e0 / s; a314 = e1 / s; a37 = e2 / s; a310 = e3 / s;
        }
        {
            float v0 = w[2], v1 = w[4], v2 = d1;
            float m = fmaxf(fmaxf(v0, v1), v2);
            float e0 = expf(v0 - m), e1 = expf(v1 - m), e2 = expf(v2 - m);
            float s = e0 + e1 + e2;
            a67 = e0 / s; a617 = e1 / s; a610 = e2 / s;
        }
        {
            float v0 = w[5], v1 = 1.0f - w[5];
            float m = fmaxf(v0, v1);
            float e0 = expf(v0 - m), e1 = expf(v1 - m);
            float s = e0 + e1;
            a920 = e0 / s; a910 = e1 / s;
        }
        {
            float v0 = w[6], v1 = 1.0f - w[9];
            float m = fmaxf(v0, v1);
            float e0 = expf(v0 - m), e1 = expf(v1 - m);
            float s = e0 + e1;
            a164 = e0 / s; a1614 = e1 / s;
        }
        {
            float v0 = w[7], v1 = 1.0f - w[10];
            float m = fmaxf(v0, v1);
            float e0 = expf(v0 - m), e1 = expf(v1 - m);
            float s = e0 + e1;
            a197 = e0 / s; a1917 = e1 / s;
        }
        {
            float v0 = w[8], v1 = 1.0f - w[11];
            float m = fmaxf(v0, v1);
            float e0 = expf(v0 - m), e1 = expf(v1 - m);
            float s = e0 + e1;
            a2210 = e0 / s; a2220 = e1 / s;
        }
        const float S6 = 1.0f / 6.0f, S36 = 1.0f / 36.0f, S216 = 1.0f / 216.0f;

        for (int l = 0; l < 32; l++) {
            g_src[l]  = make_int2(l, l);
            g_cp[l]   = make_float2(0.f, 0.f);
            g_cr[l]   = make_float2(0.f, 0.f);
            g_dsc[l]  = 1.0f;
            g_invd[l] = 1.0f;
        }
        // lane: sources, beta coefs (cp), raw coefs (cr)
        g_src[0]  = make_int2(0, 0);   g_cp[0]  = make_float2(a00, 0);          g_cr[0]  = g_cp[0];
        g_src[1]  = make_int2(0, 1);   g_cp[1]  = make_float2(a01, 0);          g_cr[1]  = g_cp[1];
        g_src[2]  = make_int2(1, 2);   g_cp[2]  = make_float2(1, 0);            g_cr[2]  = g_cp[2];
        g_src[3]  = make_int2(2, 3);   g_cp[3]  = make_float2(1, 0);            g_cr[3]  = g_cp[3];
        g_src[4]  = make_int2(3, 16);  g_cp[4]  = make_float2(a34, a164);       g_cr[4]  = g_cp[4];
        g_src[5]  = make_int2(4, 5);   g_cp[5]  = make_float2(1, 0);            g_cr[5]  = g_cp[5];
        g_src[6]  = make_int2(5, 6);   g_cp[6]  = make_float2(1, 0);            g_cr[6]  = g_cp[6];
        g_src[7]  = make_int2(3, 6);   g_cp[7]  = make_float2(a37, a67);        g_cr[7]  = g_cp[7];
        g_src[8]  = make_int2(7, 25);  g_cp[8]  = make_float2(1, 1);            g_cr[8]  = g_cp[8];
        g_src[9]  = make_int2(8, 9);   g_cp[9]  = make_float2(1, 0);            g_cr[9]  = g_cp[9];
        g_src[10] = make_int2(3, 6);   g_cp[10] = make_float2(a310, a610);      g_cr[10] = g_cp[10];
        g_src[11] = make_int2(10, 24); g_cp[11] = make_float2(1, 1);            g_cr[11] = g_cp[11];
        g_src[12] = make_int2(11, 12); g_cp[12] = make_float2(1, 0);            g_cr[12] = g_cp[12];
        g_src[13] = make_int2(12, 13); g_cp[13] = make_float2(1, 0.5f);         g_cr[13] = g_cp[13];
        g_src[14] = make_int2(3, 16);  g_cp[14] = make_float2(a314, a1614);     g_cr[14] = g_cp[14];
        g_src[15] = make_int2(14, 15); g_cp[15] = make_float2(1, 0);            g_cr[15] = g_cp[15];
        g_src[16] = make_int2(15, 16); g_cp[16] = make_float2(1, 0);            g_cr[16] = g_cp[16];
        g_src[17] = make_int2(6, 19);  g_cp[17] = make_float2(a617 * S6, a1917 * S216);
                                       g_cr[17] = make_float2(a617, a1917);
        g_src[18] = make_int2(17, 18); g_cp[18] = make_float2(1, 0);            g_cr[18] = g_cp[18];
        g_src[19] = make_int2(18, 19); g_cp[19] = make_float2(1, 0);            g_cr[19] = g_cp[19];
        g_src[20] = make_int2(9, 22);  g_cp[20] = make_float2(a920 * S6, a2220 * S216);
                                       g_cr[20] = make_float2(a920, a2220);
        g_src[21] = make_int2(20, 21); g_cp[21] = make_float2(1, 0);            g_cr[21] = g_cp[21];
        g_src[22] = make_int2(21, 22); g_cp[22] = make_float2(1, 0);            g_cr[22] = g_cp[22];
        g_src[23] = make_int2(13, 23); g_cp[23] = make_float2(0.5f * S6, S6);
                                       g_cr[23] = make_float2(0.5f, 1.0f);
        // helper lanes: 24 = partial of state 10 (terms 9,22); 25 = partial of 7 (term 19)
        g_src[24] = make_int2(9, 22);  g_cp[24] = make_float2(a910, a2210 * S36);
                                       g_cr[24] = make_float2(a910, a2210);
        g_src[25] = make_int2(19, 25); g_cp[25] = make_float2(a197 * S36, 0);
                                       g_cr[25] = make_float2(a197, 0);
        // beta scales
        g_dsc[18] = 6.0f;  g_invd[18] = S6;
        g_dsc[19] = 36.0f; g_invd[19] = S36;
        g_dsc[21] = 6.0f;  g_invd[21] = S6;
        g_dsc[22] = 36.0f; g_invd[22] = S36;
        // pi
        {
            float m = -1e30f;
            for (int i = 0; i < 24; i++) m = fmaxf(m, ik[i]);
            float e[24]; float s = 0.0f;
            for (int i = 0; i < 24; i++) { e[i] = expf(ik[i] - m); s += e[i]; }
            for (int i = 0; i < 24; i++) g_pi[i] = e[i] / s;
        }
    }
    __syncthreads();

    // Destination-state E factor per lane: lanes 0..16 -> E_state; 17..23 -> 1
    // (1/6 folded into coefs); 24 -> E10; 25 -> E7; 26..31 -> 0.
    for (int idx = tid; idx < 64 * 32; idx += blockDim.x) {
        int ctx = idx >> 5;
        int l   = idx & 31;
        int st  = (l < 17) ? l : (l == 24) ? 10 : (l == 25) ? 7 : -1;
        float val;
        if (st >= 0) {
            int pq = ctx >> 2;
            int c  = ctx & 3;
            const float* p = ew + st * 64 + pq * 4;
            float v0 = p[0], v1 = p[1], v2 = p[2], v3 = p[3];
            float m = fmaxf(fmaxf(v0, v1), fmaxf(v2, v3));
            float e0 = expf(v0 - m), e1 = expf(v1 - m),
                  e2 = expf(v2 - m), e3 = expf(v3 - m);
            float ss = e0 + e1 + e2 + e3;
            float ec = (c == 0) ? e0 : (c == 1) ? e1 : (c == 2) ? e2 : e3;
            val = ec / ss;
        } else if (l < 24) {
            val = 1.0f;
        } else {
            val = 0.0f;
        }
        g_Etab[idx] = val;
    }
}

// ---------------------------------------------------------------------------
// Forward kernel
// ---------------------------------------------------------------------------
__global__ __launch_bounds__(BLOCK)
void forward_kernel(const int* __restrict__ seq, float* __restrict__ out) {
    __shared__ __align__(16) float Tb[64 * 32];
    {
        const float4* src = reinterpret_cast<const float4*>(g_Etab);
        float4* dst = reinterpret_cast<float4*>(Tb);
        for (int i = threadIdx.x; i < 64 * 32 / 4; i += BLOCK) dst[i] = src[i];
    }
    __syncthreads();

    const unsigned FULL = 0xffffffffu;
    const int lane = threadIdx.x & 31;
    const int wid  = blockIdx.x * WPB + (threadIdx.x >> 5);

    const int2   si = g_src[lane];
    const float2 cp = g_cp[lane];
    const float  invd = g_invd[lane];
    const float* TbL = Tb + lane;

    const int4* q4 = reinterpret_cast<const int4*>(seq + wid * T_LEN);

    float beta = (lane < 24) ? g_pi[lane] : 0.0f;

    // t=1: raw-coef transition step, then beta scale.
    {
        const float2 cr = g_cr[lane];
        const float  dsc = g_dsc[lane];
        float x0 = __shfl_sync(FULL, beta, si.x);
        float x1 = __shfl_sync(FULL, beta, si.y);
        beta = dsc * fmaf(cr.y, x1, cr.x * x0);
    }

    float ll = -3.58351893845611f;   // 2 * ln(1/6)

#define STEP(EV) do { \
        float x0 = __shfl_sync(FULL, beta, si.x); \
        float x1 = __shfl_sync(FULL, beta, si.y); \
        beta = (EV) * fmaf(cp.y, x1, cp.x * x0); \
    } while (0)

    // t=2, t=3
    int4 v = q4[0];
    int ctx;
    {
        int c2 = ((v.x << 4) | (v.y << 2) | v.z) & 63;
        int c3 = ((c2 << 2) | v.w) & 63;
        float e2 = TbL[c2 << 5];
        float e3 = TbL[c3 << 5];
        STEP(e2);
        STEP(e3);
        ctx = c3;
    }

    // main loop: 4 steps per int4, seq prefetch distance 2, renorm every 8 blocks
    int4 u0 = q4[1];
    int4 u1 = q4[2];
    for (int j = 1; j < 500; ++j) {
        int jn = (j < 498) ? j + 2 : 499;
        int4 up = q4[jn];
        int c0 = ((ctx << 2) | u0.x) & 63;
        int c1 = ((c0  << 2) | u0.y) & 63;
        int c2 = ((c1  << 2) | u0.z) & 63;
        int c3 = ((c2  << 2) | u0.w) & 63;
        ctx = c3;
        float e0 = TbL[c0 << 5];
        float e1 = TbL[c1 << 5];
        float e2 = TbL[c2 << 5];
        float e3 = TbL[c3 << 5];
        STEP(e0);
        STEP(e1);
        STEP(e2);
        STEP(e3);
        if ((j & 7) == 7) {
            float t = beta;
            t += __shfl_xor_sync(FULL, t, 16);
            t += __shfl_xor_sync(FULL, t, 8);
            t += __shfl_xor_sync(FULL, t, 4);
            t += __shfl_xor_sync(FULL, t, 2);
            t += __shfl_xor_sync(FULL, t, 1);
            ll += __logf(t);
            beta *= __fdividef(1.0f, t);
        }
        u0 = u1; u1 = up;
    }
#undef STEP

    // final beta -> alpha mass correction
    {
        float t = beta * invd;
        t += __shfl_xor_sync(FULL, t, 16);
        t += __shfl_xor_sync(FULL, t, 8);
        t += __shfl_xor_sync(FULL, t, 4);
        t += __shfl_xor_sync(FULL, t, 2);
        t += __shfl_xor_sync(FULL, t, 1);
        ll += __logf(t);
    }

    if (lane == 0) out[wid] = ll;
}

// ---------------------------------------------------------------------------
// Launch
// ---------------------------------------------------------------------------
extern "C" void kernel_launch(void* const* d_in, const int* in_sizes, int n_in,
                              void* d_out, int out_size) {
    const float* transition_kernel = (const float*)d_in[0];
    const float* emission_kernel   = (const float*)d_in[1];
    const float* init_kernel       = (const float*)d_in[2];
    const int*   seq               = (const int*)d_in[3];
    float* out = (float*)d_out;

    setup_kernel<<<1, 256>>>(transition_kernel, emission_kernel, init_kernel);
    forward_kernel<<<BATCH / WPB, BLOCK>>>(seq, out);
}